// round 12
// baseline (speedup 1.0000x reference)
#include <cuda_runtime.h>
#include <cuda_bf16.h>

// Problem constants (fixed by setup_inputs)
#define B_ 64
#define N_ 1024
#define E_ 16384
#define D_ 1024
#define C_ 128

#define NB 132          // 1 block per SM (<=148) -> co-residency guaranteed
#define NT 1024
#define FULLM 0xffffffffu
#define DMAXP1 (E_ + 1) // degree value range bound

// ---------------- device scratch (static, no allocations) ----------------
// deg/flag2/flag3/flagd/nd are cleared at the END of each launch (zero-init at load).
__device__ __align__(16) int g_src[E_];
__device__ __align__(16) int g_dst[E_];
__device__ int   g_deg[N_];
__device__ int   g_nrank[N_];           // node -> degree-rank
__device__ int   g_rowptr[N_ + 1];
__device__ int   g_cursor[N_];          // atomic fill cursors (= rowptr at P2 start)
__device__ int   g_col[E_];
__device__ int   g_nbrrank[E_];         // degree-rank of neighbor, per CSR slot
__device__ int   g_flag2[N_], g_flag3[N_];
__device__ int   g_list2[N_], g_list3[N_];
__device__ int   g_c2, g_c3;
__device__ int   g_flagd[DMAXP1];       // degree-value claimed flags
__device__ int   g_degrank[DMAXP1];     // degree value -> rank
__device__ float g_dval[N_];            // rank -> degree value (as float)
__device__ int   g_nd;                  // number of distinct degree values
__device__ __align__(16) float g_h0[B_ * C_];   // relu(x@W_emb+b) per batch
__device__ __align__(16) float g_Wt[C_ * C_];   // W_conv transposed: Wt[c][k]
__device__ __align__(16) float g_w0[B_ * C_];   // (h0 @ W_conv) per batch
__device__ __align__(16) float g_G[N_ * B_ * C_];  // G[rank][b][c]
__device__ __align__(16) float g_H2[B_ * N_ * C_]; // node-indexed (frontier2 rows)
__device__ __align__(16) float g_H3[B_ * N_ * C_]; // node-indexed (frontier3 rows)

// ---------------- software grid barrier (all blocks resident) ----------------
__device__ volatile unsigned g_gen;
__device__ unsigned          g_count;

__device__ __forceinline__ void gsync(unsigned gen0, unsigned k) {
    __syncthreads();
    if (threadIdx.x == 0) {
        __threadfence();
        if (atomicAdd(&g_count, 1u) == NB - 1u) {
            g_count = 0u;
            __threadfence();
            g_gen = gen0 + k;
        } else {
            while (g_gen != gen0 + k) { __nanosleep(32); }
        }
        __threadfence();
    }
    __syncthreads();
}

// ---------------- f32x2 packed helpers (Blackwell) ---------------------------
__device__ __forceinline__ void ffma2(unsigned long long& d,
                                      unsigned long long a, unsigned long long b) {
    asm("fma.rn.f32x2 %0, %1, %2, %0;" : "+l"(d) : "l"(a), "l"(b));
}
__device__ __forceinline__ void addf2(unsigned long long& d, unsigned long long a) {
    asm("add.rn.f32x2 %0, %0, %1;" : "+l"(d) : "l"(a));
}
__device__ __forceinline__ unsigned long long pack2(float lo, float hi) {
    unsigned long long r;
    asm("mov.b64 %0, {%1, %2};" : "=l"(r) : "f"(lo), "f"(hi));
    return r;
}
__device__ __forceinline__ void unpack2(unsigned long long v, float& lo, float& hi) {
    asm("mov.b64 {%0, %1}, %2;" : "=f"(lo), "=f"(hi) : "l"(v));
}
__device__ __forceinline__ float unpack_sum(unsigned long long v) {
    float lo, hi; unpack2(v, lo, hi);
    return lo + hi;
}

// inclusive scan of one value per thread across 1024 threads (single block)
__device__ __forceinline__ int scan1(int v, int t, int* s) {
    s[t] = v;
    __syncthreads();
#pragma unroll
    for (int off = 1; off < NT; off <<= 1) {
        int u = (t >= off) ? s[t - off] : 0;
        __syncthreads();
        s[t] += u;
        __syncthreads();
    }
    int r = s[t];
    __syncthreads();
    return r;
}

__device__ __forceinline__ void compact_flags(const int* flags, int* list, int* cnt_out,
                                              int t, int* s) {
    int f = flags[t];
    int incl = scan1(f, t, s);
    if (f) list[incl - 1] = t;
    if (t == NT - 1) *cnt_out = incl;
}

__global__ __launch_bounds__(NT) void k_mega(
    const float* __restrict__ x, const void* __restrict__ eidx,
    const float* __restrict__ W_emb,  const float* __restrict__ b_emb,
    const float* __restrict__ W_conv, const float* __restrict__ b_conv,
    const float* __restrict__ W_cls,  const float* __restrict__ b_cls,
    float* __restrict__ out)
{
    __shared__ __align__(16) float sm[8192];     // 32 KB, unioned across phases
    const int t   = threadIdx.x;
    const int bid = blockIdx.x;
    const unsigned gen0 = g_gen;

    // ======== P0: embedding h0 (blocks 0..31, 2 batches, float4 W_emb)
    //          || edge convert + deg + flag3 (32..47) || W_conv transpose (48..49)
    if (bid < 32) {
        int b0 = bid * 2;
        float* xs   = sm;             // [2][1024]
        float* part = sm + 2048;      // [32][128]
        float* red8 = sm + 6144;      // [8][128]
        xs[t] = x[b0 * D_ + t];
        xs[1024 + t] = x[(b0 + 1) * D_ + t];
        __syncthreads();
        int c4 = (t & 31) * 4, ds = t >> 5;       // 32 c-quads x 32 d-slices
        int d0 = ds * 32;
        float4 A0 = {0.f, 0.f, 0.f, 0.f}, A1 = {0.f, 0.f, 0.f, 0.f};
#pragma unroll 4
        for (int d = d0; d < d0 + 32; d++) {
            float4 w = *(const float4*)&W_emb[d * C_ + c4];
            float x0 = xs[d], x1 = xs[1024 + d];
            A0.x += x0 * w.x; A0.y += x0 * w.y; A0.z += x0 * w.z; A0.w += x0 * w.w;
            A1.x += x1 * w.x; A1.y += x1 * w.y; A1.z += x1 * w.z; A1.w += x1 * w.w;
        }
        // batch 0 reduce
        *(float4*)&part[ds * 128 + c4] = A0;
        __syncthreads();
        {
            int c = t & 127, g8 = t >> 7;
            float a = part[(g8 * 4 + 0) * 128 + c] + part[(g8 * 4 + 1) * 128 + c]
                    + part[(g8 * 4 + 2) * 128 + c] + part[(g8 * 4 + 3) * 128 + c];
            red8[g8 * 128 + c] = a;
        }
        __syncthreads();
        if (t < 128) {
            float h = b_emb[t];
#pragma unroll
            for (int s = 0; s < 8; s++) h += red8[s * 128 + t];
            g_h0[b0 * C_ + t] = fmaxf(h, 0.f);
        }
        __syncthreads();
        // batch 1 reduce
        *(float4*)&part[ds * 128 + c4] = A1;
        __syncthreads();
        {
            int c = t & 127, g8 = t >> 7;
            float a = part[(g8 * 4 + 0) * 128 + c] + part[(g8 * 4 + 1) * 128 + c]
                    + part[(g8 * 4 + 2) * 128 + c] + part[(g8 * 4 + 3) * 128 + c];
            red8[g8 * 128 + c] = a;
        }
        __syncthreads();
        if (t < 128) {
            float h = b_emb[t];
#pragma unroll
            for (int s = 0; s < 8; s++) h += red8[s * 128 + t];
            g_h0[(b0 + 1) * C_ + t] = fmaxf(h, 0.f);
        }
    } else if (bid < 48) {
        int e = (bid - 32) * 1024 + t;            // 16*1024 == E_
        const unsigned* ew32 = (const unsigned*)eidx;
        int any = __syncthreads_or(ew32[2 * e + 1] != 0u);
        int is64 = !any;                          // int64 => high words all zero
        int s, d;
        if (is64) {
            const long long* p = (const long long*)eidx;
            s = (int)p[e]; d = (int)p[E_ + e];
        } else {
            const int* p = (const int*)eidx;
            s = p[e]; d = p[E_ + e];
        }
        g_src[e] = s; g_dst[e] = d;
        atomicAdd(&g_deg[d], 1);
        if (d == 0) g_flag3[s] = 1;
    } else if (bid < 50) {
        int base = (bid - 48) * 8192 + t;
#pragma unroll
        for (int j = 0; j < 8; j++) {
            int idx = base + j * 1024;
            g_Wt[(idx & 127) * 128 + (idx >> 7)] = W_conv[idx];
        }
    }
    gsync(gen0, 1);

    // ======== P1: flag2 (0..15) || rowptr+cursor scan (16) || flag3 compact (17)
    //          || rank claim (18) || w0 = h0 @ W_conv via Wt (19..50)
    if (bid < 16) {
        int e = bid * 1024 + t;
        if (g_flag3[g_dst[e]]) g_flag2[g_src[e]] = 1;
    } else if (bid == 16) {
        int d = g_deg[t];
        int incl = scan1(d, t, (int*)sm);
        g_rowptr[t + 1] = incl;
        g_cursor[t] = incl - d;                   // exclusive prefix = rowptr[t]
        if (t == 0) g_rowptr[0] = 0;
    } else if (bid == 17) {
        compact_flags(g_flag3, g_list3, &g_c3, t, (int*)sm);
    } else if (bid == 18) {
        int d = g_deg[t];                          // thread t handles node t
        int old = atomicExch(&g_flagd[d], 1);
        if (old == 0) {
            int r = atomicAdd(&g_nd, 1);
            g_degrank[d] = r;
            g_dval[r] = (float)d;
        }
        __syncthreads();
        g_nrank[t] = g_degrank[d];
    } else if (bid < 51) {
        int b0 = (bid - 19) * 2;
        float* sh0  = sm;            // [2][128]
        float* part = sm + 256;      // [2][8][128]
        if (t < 256) sh0[t] = g_h0[b0 * C_ + t];
        __syncthreads();
        int c = t & 127, ks = t >> 7;             // 8 k-slices of 16
        int k0 = ks * 16;
        float p0 = 0.f, p1 = 0.f;
#pragma unroll
        for (int k = k0; k < k0 + 16; k += 4) {
            float4 wv = *(const float4*)&g_Wt[c * 128 + k];
            p0 += sh0[k] * wv.x; p0 += sh0[k + 1] * wv.y;
            p0 += sh0[k + 2] * wv.z; p0 += sh0[k + 3] * wv.w;
            p1 += sh0[128 + k] * wv.x; p1 += sh0[128 + k + 1] * wv.y;
            p1 += sh0[128 + k + 2] * wv.z; p1 += sh0[128 + k + 3] * wv.w;
        }
        part[ks * 128 + c] = p0;
        part[1024 + ks * 128 + c] = p1;
        __syncthreads();
        if (t < 256) {
            int bb = t >> 7, cc = t & 127;
            float a = 0.f;
#pragma unroll
            for (int s = 0; s < 8; s++) a += part[bb * 1024 + s * 128 + cc];
            g_w0[(b0 + bb) * C_ + cc] = a;
        }
    }
    gsync(gen0, 2);

    // ======== P2: csrfill edge-parallel (blocks 0..15, atomic cursors)
    //          || G-table build via Wt (16..130) || flag2 compact (131)
    if (bid < 16) {
        int e = bid * 1024 + t;
        int d = g_dst[e], s = g_src[e];
        int pos = atomicAdd(&g_cursor[d], 1);
        g_col[pos] = s;
        g_nbrrank[pos] = g_nrank[s];
    } else if (bid < 131) {
        int nd = g_nd;
        int c = t & 127, rg = t >> 7;
        float bc = b_conv[c];
        float (*As)[C_] = (float (*)[C_])sm;      // [64][128], row r == batch b
        for (int rank = bid - 16; rank < nd; rank += 115) {
            float dv = g_dval[rank];
            for (int r = rg * 8; r < rg * 8 + 8; r++)
                As[r][c] = fmaxf(dv * g_w0[r * C_ + c] + bc, 0.f);
            __syncthreads();
            unsigned long long acc2[8];
#pragma unroll
            for (int r = 0; r < 8; r++) acc2[r] = 0ull;
#pragma unroll 4
            for (int k = 0; k < C_; k += 4) {
                float4 wv = *(const float4*)&g_Wt[c * 128 + k];
                unsigned long long w01 = pack2(wv.x, wv.y);
                unsigned long long w23 = pack2(wv.z, wv.w);
#pragma unroll
                for (int r = 0; r < 8; r++) {
                    const ulonglong2 av = *(const ulonglong2*)&As[rg * 8 + r][k];
                    ffma2(acc2[r], av.x, w01);
                    ffma2(acc2[r], av.y, w23);
                }
            }
#pragma unroll
            for (int r = 0; r < 8; r++)
                g_G[(rank * B_ + rg * 8 + r) * C_ + c] = unpack_sum(acc2[r]);
            __syncthreads();
        }
    } else {
        compact_flags(g_flag2, g_list2, &g_c2, t, (int*)sm);
    }
    gsync(gen0, 3);

    // ======== P3: conv2 = packed f32x2 aggregation of G rows =================
    {
        int cnt2 = g_c2;
        int items = cnt2 * 8;                     // (i2, b-octet) work items
        int gid = bid * 16 + (t >> 6);            // 2112 groups of 64 threads
        int c2i = (t & 63) * 2;                   // channel pair 2c, 2c+1
        float bc0 = b_conv[c2i], bc1 = b_conv[c2i + 1];
        for (int it = gid; it < items; it += NB * 16) {
            int i = it >> 3, b0 = (it & 7) * 8;
            int n = g_list2[i];
            int s0 = g_rowptr[n], s1 = g_rowptr[n + 1];
            unsigned long long A0 = 0ull, A1 = 0ull, A2 = 0ull, A3 = 0ull;
            unsigned long long A4 = 0ull, A5 = 0ull, A6 = 0ull, A7 = 0ull;
#pragma unroll 1
            for (int q = s0; q < s1; q++) {
                const unsigned long long* gp = (const unsigned long long*)
                    &g_G[(g_nbrrank[q] * B_ + b0) * C_ + c2i];
                addf2(A0, gp[0 * 64]); addf2(A1, gp[1 * 64]);
                addf2(A2, gp[2 * 64]); addf2(A3, gp[3 * 64]);
                addf2(A4, gp[4 * 64]); addf2(A5, gp[5 * 64]);
                addf2(A6, gp[6 * 64]); addf2(A7, gp[7 * 64]);
            }
            float* hp = &g_H2[(b0 * N_ + n) * C_ + c2i];
            const int st = N_ * C_;
            float lo, hi;
            unpack2(A0, lo, hi); *(float2*)&hp[0 * st] = make_float2(fmaxf(lo + bc0, 0.f), fmaxf(hi + bc1, 0.f));
            unpack2(A1, lo, hi); *(float2*)&hp[1 * st] = make_float2(fmaxf(lo + bc0, 0.f), fmaxf(hi + bc1, 0.f));
            unpack2(A2, lo, hi); *(float2*)&hp[2 * st] = make_float2(fmaxf(lo + bc0, 0.f), fmaxf(hi + bc1, 0.f));
            unpack2(A3, lo, hi); *(float2*)&hp[3 * st] = make_float2(fmaxf(lo + bc0, 0.f), fmaxf(hi + bc1, 0.f));
            unpack2(A4, lo, hi); *(float2*)&hp[4 * st] = make_float2(fmaxf(lo + bc0, 0.f), fmaxf(hi + bc1, 0.f));
            unpack2(A5, lo, hi); *(float2*)&hp[5 * st] = make_float2(fmaxf(lo + bc0, 0.f), fmaxf(hi + bc1, 0.f));
            unpack2(A6, lo, hi); *(float2*)&hp[6 * st] = make_float2(fmaxf(lo + bc0, 0.f), fmaxf(hi + bc1, 0.f));
            unpack2(A7, lo, hi); *(float2*)&hp[7 * st] = make_float2(fmaxf(lo + bc0, 0.f), fmaxf(hi + bc1, 0.f));
        }
    }
    gsync(gen0, 4);

    // ======== P4: conv3 fused agg + f32x2 GEMM via Wt (one 8-row tile/block) ==
    {
        int cnt3 = g_c3;
        int M3 = B_ * cnt3;
        int ntiles = (M3 + 7) >> 3;
        int grp = t >> 7, c = t & 127;
        float bc = b_conv[c];
        float (*As)[C_] = (float (*)[C_])sm;      // [8][128], group grp owns row grp
        for (int tile = bid; tile < ntiles; tile += NB) {
            int rr = tile * 8 + grp;
            int b = 0, i = 0;
            float acc = 0.f;
            if (rr < M3) {
                b = rr / cnt3; i = rr - b * cnt3;
                int n = g_list3[i];
                int s0 = g_rowptr[n], s1 = g_rowptr[n + 1];
#pragma unroll 8
                for (int q = s0; q < s1; q++)
                    acc += g_H2[(b * N_ + g_col[q]) * C_ + c];
            }
            As[grp][c] = acc;
            __syncthreads();
            unsigned long long acc2 = 0ull;
#pragma unroll 4
            for (int k = 0; k < C_; k += 4) {
                float4 wv = *(const float4*)&g_Wt[c * 128 + k];
                unsigned long long w01 = pack2(wv.x, wv.y);
                unsigned long long w23 = pack2(wv.z, wv.w);
                const ulonglong2 av = *(const ulonglong2*)&As[grp][k];
                ffma2(acc2, av.x, w01);
                ffma2(acc2, av.y, w23);
            }
            if (rr < M3)
                g_H3[(b * N_ + g_list3[i]) * C_ + c] =
                    fmaxf(unpack_sum(acc2) + bc, 0.f);
            __syncthreads();
        }
    }
    gsync(gen0, 5);

    // ======== P5: conv4 agg (node 0) + GEMM + classifier (blocks 0..63)
    //          || clear scratch for next launch (blocks 64..67)
    if (bid < B_) {
        float* part = sm;            // [8][128]
        float* s4   = sm + 1024;     // [128]
        float* red  = sm + 1152;     // [128]
        int ks = t >> 7, c = t & 127;
        int s0 = g_rowptr[0], s1 = g_rowptr[1];
        float acc = 0.f;
        for (int q = s0 + ks; q < s1; q += 8)
            acc += g_H3[(bid * N_ + g_col[q]) * C_ + c];
        part[ks * 128 + c] = acc;
        __syncthreads();
        if (t < 128) {
            float a = 0.f;
#pragma unroll
            for (int s = 0; s < 8; s++) a += part[s * 128 + t];
            s4[t] = a;
        }
        __syncthreads();
        int k0 = ks * 16;
        float p = 0.f;
#pragma unroll
        for (int k = k0; k < k0 + 16; k += 4) {
            float4 wv = *(const float4*)&g_Wt[c * 128 + k];
            p += s4[k] * wv.x; p += s4[k + 1] * wv.y;
            p += s4[k + 2] * wv.z; p += s4[k + 3] * wv.w;
        }
        __syncthreads();
        part[ks * 128 + c] = p;
        __syncthreads();
        if (t < 128) {
            float a2 = b_conv[t];
#pragma unroll
            for (int s = 0; s < 8; s++) a2 += part[s * 128 + t];
            red[t] = fmaxf(a2, 0.f) * W_cls[t];
        }
        __syncthreads();
#pragma unroll
        for (int off = 64; off > 0; off >>= 1) {
            if (t < off) red[t] += red[t + off];
            __syncthreads();
        }
        if (t == 0) out[bid] = red[0] + b_cls[0];
    } else if (bid == 64) {
        g_deg[t] = 0;
    } else if (bid == 65) {
        g_flag2[t] = 0;
    } else if (bid == 66) {
        g_flag3[t] = 0;
    } else if (bid == 67) {
        int nd = g_nd;
        if (t < nd) g_flagd[(int)g_dval[t]] = 0;
        __syncthreads();
        if (t == 0) g_nd = 0;
    }
}

extern "C" void kernel_launch(void* const* d_in, const int* in_sizes, int n_in,
                              void* d_out, int out_size) {
    (void)in_sizes; (void)n_in; (void)out_size;
    const float* x      = (const float*)d_in[0];
    const void*  eidx   = d_in[1];
    const float* W_emb  = (const float*)d_in[2];
    const float* b_emb  = (const float*)d_in[3];
    const float* W_conv = (const float*)d_in[4];
    const float* b_conv = (const float*)d_in[5];
    const float* W_cls  = (const float*)d_in[6];
    const float* b_cls  = (const float*)d_in[7];
    float* out = (float*)d_out;

    k_mega<<<NB, NT>>>(x, eidx, W_emb, b_emb, W_conv, b_conv, W_cls, b_cls, out);
}

// round 13
// speedup vs baseline: 1.6827x; 1.6827x over previous
#include <cuda_runtime.h>
#include <cuda_bf16.h>

// Problem constants (fixed by setup_inputs)
#define B_ 64
#define N_ 1024
#define E_ 16384
#define D_ 1024
#define C_ 128

#define NB 132          // 1 block per SM (<=148) -> co-residency guaranteed
#define NT 1024
#define FULLM 0xffffffffu
#define DMAXP1 (E_ + 1) // degree value range bound

// ---------------- device scratch (static, no allocations) ----------------
// deg/flag2/flag3/flagd/nd are cleared at the END of each launch (zero-init at load).
__device__ __align__(16) int g_src[E_];
__device__ __align__(16) int g_dst[E_];
__device__ int   g_deg[N_];
__device__ int   g_nrank[N_];           // node -> degree-rank
__device__ int   g_rowptr[N_ + 1];
__device__ int   g_cursor[N_];          // atomic fill cursors (= rowptr at P2 start)
__device__ int   g_col[E_];
__device__ int   g_nbrrank[E_];         // degree-rank of neighbor, per CSR slot
__device__ int   g_flag2[N_], g_flag3[N_];
__device__ int   g_list2[N_], g_list3[N_];
__device__ int   g_c2, g_c3;
__device__ int   g_flagd[DMAXP1];       // degree-value claimed flags
__device__ int   g_degrank[DMAXP1];     // degree value -> rank
__device__ float g_dval[N_];            // rank -> degree value (as float)
__device__ int   g_nd;                  // number of distinct degree values
__device__ __align__(16) float g_w0[B_ * C_];      // (h0 @ W_conv) per batch
__device__ __align__(16) float g_G[N_ * B_ * C_];  // G[rank][b][c]
__device__ __align__(16) float g_H2[B_ * N_ * C_]; // node-indexed (frontier2 rows)
__device__ __align__(16) float g_H3[B_ * N_ * C_]; // node-indexed (frontier3 rows)

// ---------------- software grid barrier (all blocks resident) ----------------
__device__ volatile unsigned g_gen;
__device__ unsigned          g_count;

__device__ __forceinline__ void gsync(unsigned gen0, unsigned k) {
    __syncthreads();
    if (threadIdx.x == 0) {
        __threadfence();
        if (atomicAdd(&g_count, 1u) == NB - 1u) {
            g_count = 0u;
            __threadfence();
            g_gen = gen0 + k;
        } else {
            while (g_gen != gen0 + k) { __nanosleep(32); }
        }
        __threadfence();
    }
    __syncthreads();
}

// ---------------- f32x2 packed helpers (Blackwell) ---------------------------
__device__ __forceinline__ void ffma2(unsigned long long& d,
                                      unsigned long long a, unsigned long long b) {
    asm("fma.rn.f32x2 %0, %1, %2, %0;" : "+l"(d) : "l"(a), "l"(b));
}
__device__ __forceinline__ void addf2(unsigned long long& d, unsigned long long a) {
    asm("add.rn.f32x2 %0, %0, %1;" : "+l"(d) : "l"(a));
}
__device__ __forceinline__ unsigned long long pack2(float lo, float hi) {
    unsigned long long r;
    asm("mov.b64 %0, {%1, %2};" : "=l"(r) : "f"(lo), "f"(hi));
    return r;
}
__device__ __forceinline__ void unpack2(unsigned long long v, float& lo, float& hi) {
    asm("mov.b64 {%0, %1}, %2;" : "=f"(lo), "=f"(hi) : "l"(v));
}
__device__ __forceinline__ float unpack_sum(unsigned long long v) {
    float lo, hi; unpack2(v, lo, hi);
    return lo + hi;
}

// inclusive scan of one value per thread across 1024 threads (single block)
__device__ __forceinline__ int scan1(int v, int t, int* s) {
    s[t] = v;
    __syncthreads();
#pragma unroll
    for (int off = 1; off < NT; off <<= 1) {
        int u = (t >= off) ? s[t - off] : 0;
        __syncthreads();
        s[t] += u;
        __syncthreads();
    }
    int r = s[t];
    __syncthreads();
    return r;
}

__device__ __forceinline__ void compact_flags(const int* flags, int* list, int* cnt_out,
                                              int t, int* s) {
    int f = flags[t];
    int incl = scan1(f, t, s);
    if (f) list[incl - 1] = t;
    if (t == NT - 1) *cnt_out = incl;
}

__global__ __launch_bounds__(NT) void k_mega(
    const float* __restrict__ x, const void* __restrict__ eidx,
    const float* __restrict__ W_emb,  const float* __restrict__ b_emb,
    const float* __restrict__ W_conv, const float* __restrict__ b_conv,
    const float* __restrict__ W_cls,  const float* __restrict__ b_cls,
    float* __restrict__ out)
{
    __shared__ __align__(16) float sm[8192];     // 32 KB, unioned across phases
    const int t   = threadIdx.x;
    const int bid = blockIdx.x;
    const unsigned gen0 = g_gen;

    // ======== P0: embedding + w0 (blocks 0..31, 2 batches, float4 W_emb)
    //          || edge convert + deg + flag3 (blocks 32..47)
    if (bid < 32) {
        int b0 = bid * 2;
        float* xs   = sm;             // [2][1024]
        float* part = sm + 2048;      // [32][128]
        float* h0   = sm + 6144;      // [2][128]
        xs[t] = x[b0 * D_ + t];
        xs[1024 + t] = x[(b0 + 1) * D_ + t];
        __syncthreads();
        int c4 = (t & 31) * 4, ds = t >> 5;       // 32 c-quads x 32 d-slices
        int d0 = ds * 32;
        float4 A0 = {0.f, 0.f, 0.f, 0.f}, A1 = {0.f, 0.f, 0.f, 0.f};
#pragma unroll 4
        for (int d = d0; d < d0 + 32; d++) {
            float4 w = *(const float4*)&W_emb[d * C_ + c4];   // coalesced 512B/warp
            float x0 = xs[d], x1 = xs[1024 + d];
            A0.x += x0 * w.x; A0.y += x0 * w.y; A0.z += x0 * w.z; A0.w += x0 * w.w;
            A1.x += x1 * w.x; A1.y += x1 * w.y; A1.z += x1 * w.z; A1.w += x1 * w.w;
        }
        // batch 0 reduce
        *(float4*)&part[ds * 128 + c4] = A0;
        __syncthreads();
        {
            int c = t & 127, g8 = t >> 7;
            float a = part[(g8 * 4 + 0) * 128 + c] + part[(g8 * 4 + 1) * 128 + c]
                    + part[(g8 * 4 + 2) * 128 + c] + part[(g8 * 4 + 3) * 128 + c];
            __syncthreads();
            part[g8 * 128 + c] = a;               // reuse rows 0..7
            __syncthreads();
            if (t < 128) {
                float h = b_emb[t];
#pragma unroll
                for (int s = 0; s < 8; s++) h += part[s * 128 + t];
                h0[t] = fmaxf(h, 0.f);
            }
        }
        __syncthreads();
        // batch 1 reduce
        *(float4*)&part[ds * 128 + c4] = A1;
        __syncthreads();
        {
            int c = t & 127, g8 = t >> 7;
            float a = part[(g8 * 4 + 0) * 128 + c] + part[(g8 * 4 + 1) * 128 + c]
                    + part[(g8 * 4 + 2) * 128 + c] + part[(g8 * 4 + 3) * 128 + c];
            __syncthreads();
            part[g8 * 128 + c] = a;
            __syncthreads();
            if (t < 128) {
                float h = b_emb[t];
#pragma unroll
                for (int s = 0; s < 8; s++) h += part[s * 128 + t];
                h0[128 + t] = fmaxf(h, 0.f);
            }
        }
        __syncthreads();
        // w0[b] = h0[b] @ W_conv, 8 k-slices of 16, coalesced scalar W_conv loads
        {
            int c = t & 127, ks = t >> 7;
            int k0 = ks * 16;
            float p0 = 0.f, p1 = 0.f;
#pragma unroll
            for (int k = k0; k < k0 + 16; k++) {
                float w = W_conv[k * C_ + c];     // coalesced 128B/warp
                p0 += h0[k] * w;
                p1 += h0[128 + k] * w;
            }
            __syncthreads();
            part[ks * 128 + c] = p0;
            part[1024 + ks * 128 + c] = p1;
            __syncthreads();
            if (t < 256) {
                int bb = t >> 7, cc = t & 127;
                float a = 0.f;
#pragma unroll
                for (int s = 0; s < 8; s++) a += part[bb * 1024 + s * 128 + cc];
                g_w0[(b0 + bb) * C_ + cc] = a;
            }
        }
    } else if (bid < 48) {
        int e = (bid - 32) * 1024 + t;            // 16*1024 == E_
        const unsigned* ew32 = (const unsigned*)eidx;
        int any = __syncthreads_or(ew32[2 * e + 1] != 0u);
        int is64 = !any;                          // int64 => high words all zero
        int s, d;
        if (is64) {
            const long long* p = (const long long*)eidx;
            s = (int)p[e]; d = (int)p[E_ + e];
        } else {
            const int* p = (const int*)eidx;
            s = p[e]; d = p[E_ + e];
        }
        g_src[e] = s; g_dst[e] = d;
        atomicAdd(&g_deg[d], 1);
        if (d == 0) g_flag3[s] = 1;
    }
    gsync(gen0, 1);

    // ======== P1: flag2 (0..15) || rowptr+cursor scan (16) || flag3 compact (17)
    //          || degree-rank claim + node-rank (18)
    if (bid < 16) {
        int e = bid * 1024 + t;
        if (g_flag3[g_dst[e]]) g_flag2[g_src[e]] = 1;
    } else if (bid == 16) {
        int d = g_deg[t];
        int incl = scan1(d, t, (int*)sm);
        g_rowptr[t + 1] = incl;
        g_cursor[t] = incl - d;                   // exclusive prefix = rowptr[t]
        if (t == 0) g_rowptr[0] = 0;
    } else if (bid == 17) {
        compact_flags(g_flag3, g_list3, &g_c3, t, (int*)sm);
    } else if (bid == 18) {
        int d = g_deg[t];                          // thread t handles node t
        int old = atomicExch(&g_flagd[d], 1);
        if (old == 0) {
            int r = atomicAdd(&g_nd, 1);
            g_degrank[d] = r;
            g_dval[r] = (float)d;
        }
        __syncthreads();
        g_nrank[t] = g_degrank[d];
    }
    gsync(gen0, 2);

    // ======== P2: csrfill edge-parallel (blocks 0..15, atomic cursors)
    //          || G-table build (16..130) || flag2 compact (131)
    if (bid < 16) {
        int e = bid * 1024 + t;
        int d = g_dst[e], s = g_src[e];
        int pos = atomicAdd(&g_cursor[d], 1);
        g_col[pos] = s;
        g_nbrrank[pos] = g_nrank[s];
    } else if (bid < 131) {
        int nd = g_nd;
        int c = t & 127, rg = t >> 7;
        float bc = b_conv[c];
        float (*As)[C_] = (float (*)[C_])sm;      // [64][128], row r == batch b
        for (int rank = bid - 16; rank < nd; rank += 115) {
            float dv = g_dval[rank];
            for (int r = rg * 8; r < rg * 8 + 8; r++)
                As[r][c] = fmaxf(dv * g_w0[r * C_ + c] + bc, 0.f);
            __syncthreads();
            unsigned long long acc2[8];
#pragma unroll
            for (int r = 0; r < 8; r++) acc2[r] = 0ull;
#pragma unroll 4
            for (int k = 0; k < C_; k += 4) {
                unsigned long long w01 = pack2(W_conv[(k + 0) * C_ + c],
                                               W_conv[(k + 1) * C_ + c]);
                unsigned long long w23 = pack2(W_conv[(k + 2) * C_ + c],
                                               W_conv[(k + 3) * C_ + c]);
#pragma unroll
                for (int r = 0; r < 8; r++) {
                    const ulonglong2 av = *(const ulonglong2*)&As[rg * 8 + r][k];
                    ffma2(acc2[r], av.x, w01);
                    ffma2(acc2[r], av.y, w23);
                }
            }
#pragma unroll
            for (int r = 0; r < 8; r++)
                g_G[(rank * B_ + rg * 8 + r) * C_ + c] = unpack_sum(acc2[r]);
            __syncthreads();
        }
    } else {
        compact_flags(g_flag2, g_list2, &g_c2, t, (int*)sm);
    }
    gsync(gen0, 3);

    // ======== P3: conv2 = packed f32x2 aggregation of G rows (coalesced) ======
    {
        int cnt2 = g_c2;
        int items = cnt2 * 8;                     // (i2, b-octet) work items
        int gid = bid * 16 + (t >> 6);            // 2112 groups of 64 threads
        int c2i = (t & 63) * 2;                   // channel pair 2c, 2c+1
        float bc0 = b_conv[c2i], bc1 = b_conv[c2i + 1];
        for (int it = gid; it < items; it += NB * 16) {
            int i = it >> 3, b0 = (it & 7) * 8;
            int n = g_list2[i];
            int s0 = g_rowptr[n], s1 = g_rowptr[n + 1];
            unsigned long long A0 = 0ull, A1 = 0ull, A2 = 0ull, A3 = 0ull;
            unsigned long long A4 = 0ull, A5 = 0ull, A6 = 0ull, A7 = 0ull;
#pragma unroll 1
            for (int q = s0; q < s1; q++) {
                const unsigned long long* gp = (const unsigned long long*)
                    &g_G[(g_nbrrank[q] * B_ + b0) * C_ + c2i];
                addf2(A0, gp[0 * 64]); addf2(A1, gp[1 * 64]);
                addf2(A2, gp[2 * 64]); addf2(A3, gp[3 * 64]);
                addf2(A4, gp[4 * 64]); addf2(A5, gp[5 * 64]);
                addf2(A6, gp[6 * 64]); addf2(A7, gp[7 * 64]);
            }
            float* hp = &g_H2[(b0 * N_ + n) * C_ + c2i];
            const int st = N_ * C_;
            float lo, hi;
            unpack2(A0, lo, hi); *(float2*)&hp[0 * st] = make_float2(fmaxf(lo + bc0, 0.f), fmaxf(hi + bc1, 0.f));
            unpack2(A1, lo, hi); *(float2*)&hp[1 * st] = make_float2(fmaxf(lo + bc0, 0.f), fmaxf(hi + bc1, 0.f));
            unpack2(A2, lo, hi); *(float2*)&hp[2 * st] = make_float2(fmaxf(lo + bc0, 0.f), fmaxf(hi + bc1, 0.f));
            unpack2(A3, lo, hi); *(float2*)&hp[3 * st] = make_float2(fmaxf(lo + bc0, 0.f), fmaxf(hi + bc1, 0.f));
            unpack2(A4, lo, hi); *(float2*)&hp[4 * st] = make_float2(fmaxf(lo + bc0, 0.f), fmaxf(hi + bc1, 0.f));
            unpack2(A5, lo, hi); *(float2*)&hp[5 * st] = make_float2(fmaxf(lo + bc0, 0.f), fmaxf(hi + bc1, 0.f));
            unpack2(A6, lo, hi); *(float2*)&hp[6 * st] = make_float2(fmaxf(lo + bc0, 0.f), fmaxf(hi + bc1, 0.f));
            unpack2(A7, lo, hi); *(float2*)&hp[7 * st] = make_float2(fmaxf(lo + bc0, 0.f), fmaxf(hi + bc1, 0.f));
        }
    }
    gsync(gen0, 4);

    // ======== P4: conv3 fused agg + f32x2 GEMM + relu (one 8-row tile/block) ==
    {
        int cnt3 = g_c3;
        int M3 = B_ * cnt3;
        int ntiles = (M3 + 7) >> 3;
        int grp = t >> 7, c = t & 127;
        float bc = b_conv[c];
        float (*As)[C_] = (float (*)[C_])sm;      // [8][128], group grp owns row grp
        for (int tile = bid; tile < ntiles; tile += NB) {
            int rr = tile * 8 + grp;
            int b = 0, i = 0;
            float acc = 0.f;
            if (rr < M3) {
                b = rr / cnt3; i = rr - b * cnt3;
                int n = g_list3[i];
                int s0 = g_rowptr[n], s1 = g_rowptr[n + 1];
#pragma unroll 8
                for (int q = s0; q < s1; q++)
                    acc += g_H2[(b * N_ + g_col[q]) * C_ + c];
            }
            As[grp][c] = acc;
            __syncthreads();
            unsigned long long acc2 = 0ull;
#pragma unroll 4
            for (int k = 0; k < C_; k += 4) {
                unsigned long long w01 = pack2(W_conv[(k + 0) * C_ + c],
                                               W_conv[(k + 1) * C_ + c]);
                unsigned long long w23 = pack2(W_conv[(k + 2) * C_ + c],
                                               W_conv[(k + 3) * C_ + c]);
                const ulonglong2 av = *(const ulonglong2*)&As[grp][k];
                ffma2(acc2, av.x, w01);
                ffma2(acc2, av.y, w23);
            }
            if (rr < M3)
                g_H3[(b * N_ + g_list3[i]) * C_ + c] =
                    fmaxf(unpack_sum(acc2) + bc, 0.f);
            __syncthreads();
        }
    }
    gsync(gen0, 5);

    // ======== P5: conv4 agg (node 0) + GEMM + classifier (blocks 0..63)
    //          || clear scratch for next launch (blocks 64..67)
    if (bid < B_) {
        float* part = sm;            // [8][128]
        float* s4   = sm + 1024;     // [128]
        float* red  = sm + 1152;     // [128]
        int ks = t >> 7, c = t & 127;
        int s0 = g_rowptr[0], s1 = g_rowptr[1];
        float acc = 0.f;
        for (int q = s0 + ks; q < s1; q += 8)
            acc += g_H3[(bid * N_ + g_col[q]) * C_ + c];
        part[ks * 128 + c] = acc;
        __syncthreads();
        if (t < 128) {
            float a = 0.f;
#pragma unroll
            for (int s = 0; s < 8; s++) a += part[s * 128 + t];
            s4[t] = a;
        }
        __syncthreads();
        int k0 = ks * 16;
        float p = 0.f;
#pragma unroll
        for (int k = k0; k < k0 + 16; k++) p += s4[k] * W_conv[k * C_ + c];
        __syncthreads();
        part[ks * 128 + c] = p;
        __syncthreads();
        if (t < 128) {
            float a2 = b_conv[t];
#pragma unroll
            for (int s = 0; s < 8; s++) a2 += part[s * 128 + t];
            red[t] = fmaxf(a2, 0.f) * W_cls[t];
        }
        __syncthreads();
#pragma unroll
        for (int off = 64; off > 0; off >>= 1) {
            if (t < off) red[t] += red[t + off];
            __syncthreads();
        }
        if (t == 0) out[bid] = red[0] + b_cls[0];
    } else if (bid == 64) {
        g_deg[t] = 0;
    } else if (bid == 65) {
        g_flag2[t] = 0;
    } else if (bid == 66) {
        g_flag3[t] = 0;
    } else if (bid == 67) {
        int nd = g_nd;
        if (t < nd) g_flagd[(int)g_dval[t]] = 0;
        __syncthreads();
        if (t == 0) g_nd = 0;
    }
}

extern "C" void kernel_launch(void* const* d_in, const int* in_sizes, int n_in,
                              void* d_out, int out_size) {
    (void)in_sizes; (void)n_in; (void)out_size;
    const float* x      = (const float*)d_in[0];
    const void*  eidx   = d_in[1];
    const float* W_emb  = (const float*)d_in[2];
    const float* b_emb  = (const float*)d_in[3];
    const float* W_conv = (const float*)d_in[4];
    const float* b_conv = (const float*)d_in[5];
    const float* W_cls  = (const float*)d_in[6];
    const float* b_cls  = (const float*)d_in[7];
    float* out = (float*)d_out;

    k_mega<<<NB, NT>>>(x, eidx, W_emb, b_emb, W_conv, b_conv, W_cls, b_cls, out);
}

// round 14
// speedup vs baseline: 1.7098x; 1.0161x over previous
#include <cuda_runtime.h>
#include <cuda_bf16.h>

// Problem constants (fixed by setup_inputs)
#define B_ 64
#define N_ 1024
#define E_ 16384
#define D_ 1024
#define C_ 128

#define NB 132          // 1 block per SM (<=148) -> co-residency guaranteed
#define NT 1024
#define FULLM 0xffffffffu
#define DMAXP1 (E_ + 1) // degree value range bound

// ---------------- device scratch (static, no allocations) ----------------
// deg/flag2/flag3/flagd/nd are cleared at the END of each launch (zero-init at load).
__device__ __align__(16) int g_src[E_];
__device__ __align__(16) int g_dst[E_];
__device__ int   g_deg[N_];
__device__ int   g_nrank[N_];           // node -> degree-rank
__device__ int   g_rowptr[N_ + 1];
__device__ int   g_cursor[N_];          // atomic fill cursors (= rowptr at P2 start)
__device__ int   g_col[E_];
__device__ int   g_nbrrank[E_];         // degree-rank of neighbor, per CSR slot
__device__ int   g_flag2[N_], g_flag3[N_];
__device__ int   g_list2[N_], g_list3[N_];
__device__ int   g_c2, g_c3;
__device__ int   g_flagd[DMAXP1];       // degree-value claimed flags
__device__ int   g_degrank[DMAXP1];     // degree value -> rank
__device__ float g_dval[N_];            // rank -> degree value (as float)
__device__ int   g_nd;                  // number of distinct degree values
__device__ __align__(16) float g_w0[B_ * C_];      // (h0 @ W_conv) per batch
__device__ __align__(16) float g_G[N_ * B_ * C_];  // G[rank][b][c]
__device__ __align__(16) float g_H2[B_ * N_ * C_]; // node-indexed (frontier2 rows)
__device__ __align__(16) float g_H3[B_ * N_ * C_]; // node-indexed (frontier3 rows)

// ---------------- software grid barrier (all blocks resident) ----------------
__device__ volatile unsigned g_gen;
__device__ unsigned          g_count;

__device__ __forceinline__ void gsync(unsigned gen0, unsigned k) {
    __syncthreads();
    if (threadIdx.x == 0) {
        __threadfence();
        if (atomicAdd(&g_count, 1u) == NB - 1u) {
            g_count = 0u;
            __threadfence();
            g_gen = gen0 + k;
        } else {
            while (g_gen != gen0 + k) { __nanosleep(32); }
        }
        __threadfence();
    }
    __syncthreads();
}

// ---------------- f32x2 packed helpers (Blackwell) ---------------------------
__device__ __forceinline__ void ffma2(unsigned long long& d,
                                      unsigned long long a, unsigned long long b) {
    asm("fma.rn.f32x2 %0, %1, %2, %0;" : "+l"(d) : "l"(a), "l"(b));
}
__device__ __forceinline__ void addf2(unsigned long long& d, unsigned long long a) {
    asm("add.rn.f32x2 %0, %0, %1;" : "+l"(d) : "l"(a));
}
__device__ __forceinline__ unsigned long long pack2(float lo, float hi) {
    unsigned long long r;
    asm("mov.b64 %0, {%1, %2};" : "=l"(r) : "f"(lo), "f"(hi));
    return r;
}
__device__ __forceinline__ void unpack2(unsigned long long v, float& lo, float& hi) {
    asm("mov.b64 {%0, %1}, %2;" : "=f"(lo), "=f"(hi) : "l"(v));
}
__device__ __forceinline__ float unpack_sum(unsigned long long v) {
    float lo, hi; unpack2(v, lo, hi);
    return lo + hi;
}

// inclusive scan across 1024 threads: shfl warp scan + warp-sum scan (2 barriers)
__device__ __forceinline__ int scan1(int v, int t, int* s) {
    int lane = t & 31, w = t >> 5;               // 32 warps
    int inc = v;
#pragma unroll
    for (int off = 1; off < 32; off <<= 1) {
        int u = __shfl_up_sync(FULLM, inc, off);
        if (lane >= off) inc += u;
    }
    if (lane == 31) s[w] = inc;
    __syncthreads();
    if (w == 0) {
        int x = s[lane];
#pragma unroll
        for (int off = 1; off < 32; off <<= 1) {
            int u = __shfl_up_sync(FULLM, x, off);
            if (lane >= off) x += u;
        }
        s[lane] = x;
    }
    __syncthreads();
    return inc + (w ? s[w - 1] : 0);
}

__device__ __forceinline__ void compact_flags(const int* flags, int* list, int* cnt_out,
                                              int t, int* s) {
    int f = flags[t];
    int incl = scan1(f, t, s);
    if (f) list[incl - 1] = t;
    if (t == NT - 1) *cnt_out = incl;
}

__global__ __launch_bounds__(NT) void k_mega(
    const float* __restrict__ x, const void* __restrict__ eidx,
    const float* __restrict__ W_emb,  const float* __restrict__ b_emb,
    const float* __restrict__ W_conv, const float* __restrict__ b_conv,
    const float* __restrict__ W_cls,  const float* __restrict__ b_cls,
    float* __restrict__ out)
{
    __shared__ __align__(16) float sm[8192];     // 32 KB, unioned across phases
    const int t   = threadIdx.x;
    const int bid = blockIdx.x;
    const unsigned gen0 = g_gen;

    // ======== P0: embedding + w0 (blocks 0..63, ONE batch each, float4 W_emb)
    //          || edge convert + deg + flag3 (blocks 64..79)
    if (bid < 64) {
        int b = bid;
        float* xs   = sm;             // [1024]
        float* part = sm + 1024;      // [32][128]
        float* h0   = sm + 5120;      // [128]
        xs[t] = x[b * D_ + t];
        __syncthreads();
        int c4 = (t & 31) * 4, ds = t >> 5;       // 32 c-quads x 32 d-slices
        int d0 = ds * 32;
        float4 A = {0.f, 0.f, 0.f, 0.f};
#pragma unroll 4
        for (int d = d0; d < d0 + 32; d++) {
            float4 w = *(const float4*)&W_emb[d * C_ + c4];   // coalesced 512B/warp
            float x0 = xs[d];
            A.x += x0 * w.x; A.y += x0 * w.y; A.z += x0 * w.z; A.w += x0 * w.w;
        }
        *(float4*)&part[ds * 128 + c4] = A;
        __syncthreads();
        int c = t & 127, g8 = t >> 7;
        float a = part[(g8 * 4 + 0) * 128 + c] + part[(g8 * 4 + 1) * 128 + c]
                + part[(g8 * 4 + 2) * 128 + c] + part[(g8 * 4 + 3) * 128 + c];
        __syncthreads();
        part[g8 * 128 + c] = a;                   // reuse rows 0..7
        __syncthreads();
        if (t < 128) {
            float h = b_emb[t];
#pragma unroll
            for (int s = 0; s < 8; s++) h += part[s * 128 + t];
            h0[t] = fmaxf(h, 0.f);
        }
        __syncthreads();
        // w0[b] = h0 @ W_conv, 8 k-slices of 16, coalesced scalar W_conv loads
        int ks = g8, k0 = ks * 16;
        float p = 0.f;
#pragma unroll
        for (int k = k0; k < k0 + 16; k++)
            p += h0[k] * W_conv[k * C_ + c];      // coalesced 128B/warp
        __syncthreads();
        part[ks * 128 + c] = p;
        __syncthreads();
        if (t < 128) {
            float a2 = 0.f;
#pragma unroll
            for (int s = 0; s < 8; s++) a2 += part[s * 128 + t];
            g_w0[b * C_ + t] = a2;
        }
    } else if (bid < 80) {
        int e = (bid - 64) * 1024 + t;            // 16*1024 == E_
        const unsigned* ew32 = (const unsigned*)eidx;
        int any = __syncthreads_or(ew32[2 * e + 1] != 0u);
        int is64 = !any;                          // int64 => high words all zero
        int s, d;
        if (is64) {
            const long long* p = (const long long*)eidx;
            s = (int)p[e]; d = (int)p[E_ + e];
        } else {
            const int* p = (const int*)eidx;
            s = p[e]; d = p[E_ + e];
        }
        g_src[e] = s; g_dst[e] = d;
        atomicAdd(&g_deg[d], 1);
        if (d == 0) g_flag3[s] = 1;
    }
    gsync(gen0, 1);

    // ======== P1: flag2 (0..15) || rowptr+cursor scan (16) || flag3 compact (17)
    //          || degree-rank claim + node-rank (18)
    if (bid < 16) {
        int e = bid * 1024 + t;
        if (g_flag3[g_dst[e]]) g_flag2[g_src[e]] = 1;
    } else if (bid == 16) {
        int d = g_deg[t];
        int incl = scan1(d, t, (int*)sm);
        g_rowptr[t + 1] = incl;
        g_cursor[t] = incl - d;                   // exclusive prefix = rowptr[t]
        if (t == 0) g_rowptr[0] = 0;
    } else if (bid == 17) {
        compact_flags(g_flag3, g_list3, &g_c3, t, (int*)sm);
    } else if (bid == 18) {
        int d = g_deg[t];                          // thread t handles node t
        int old = atomicExch(&g_flagd[d], 1);
        if (old == 0) {
            int r = atomicAdd(&g_nd, 1);
            g_degrank[d] = r;
            g_dval[r] = (float)d;
        }
        __syncthreads();
        g_nrank[t] = g_degrank[d];
    }
    gsync(gen0, 2);

    // ======== P2: csrfill edge-parallel (blocks 0..15, atomic cursors)
    //          || G-table build (16..130) || flag2 compact (131)
    if (bid < 16) {
        int e = bid * 1024 + t;
        int d = g_dst[e], s = g_src[e];
        int pos = atomicAdd(&g_cursor[d], 1);
        g_col[pos] = s;
        g_nbrrank[pos] = g_nrank[s];
    } else if (bid < 131) {
        int nd = g_nd;
        int c = t & 127, rg = t >> 7;
        float bc = b_conv[c];
        float (*As)[C_] = (float (*)[C_])sm;      // [64][128], row r == batch b
        for (int rank = bid - 16; rank < nd; rank += 115) {
            float dv = g_dval[rank];
            for (int r = rg * 8; r < rg * 8 + 8; r++)
                As[r][c] = fmaxf(dv * g_w0[r * C_ + c] + bc, 0.f);
            __syncthreads();
            unsigned long long acc2[8];
#pragma unroll
            for (int r = 0; r < 8; r++) acc2[r] = 0ull;
#pragma unroll 4
            for (int k = 0; k < C_; k += 4) {
                unsigned long long w01 = pack2(W_conv[(k + 0) * C_ + c],
                                               W_conv[(k + 1) * C_ + c]);
                unsigned long long w23 = pack2(W_conv[(k + 2) * C_ + c],
                                               W_conv[(k + 3) * C_ + c]);
#pragma unroll
                for (int r = 0; r < 8; r++) {
                    const ulonglong2 av = *(const ulonglong2*)&As[rg * 8 + r][k];
                    ffma2(acc2[r], av.x, w01);
                    ffma2(acc2[r], av.y, w23);
                }
            }
#pragma unroll
            for (int r = 0; r < 8; r++)
                g_G[(rank * B_ + rg * 8 + r) * C_ + c] = unpack_sum(acc2[r]);
            __syncthreads();
        }
    } else {
        compact_flags(g_flag2, g_list2, &g_c2, t, (int*)sm);
    }
    gsync(gen0, 3);

    // ======== P3: conv2 = packed f32x2 aggregation of G rows (coalesced) ======
    {
        int cnt2 = g_c2;
        int items = cnt2 * 8;                     // (i2, b-octet) work items
        int gid = bid * 16 + (t >> 6);            // 2112 groups of 64 threads
        int c2i = (t & 63) * 2;                   // channel pair 2c, 2c+1
        float bc0 = b_conv[c2i], bc1 = b_conv[c2i + 1];
        for (int it = gid; it < items; it += NB * 16) {
            int i = it >> 3, b0 = (it & 7) * 8;
            int n = g_list2[i];
            int s0 = g_rowptr[n], s1 = g_rowptr[n + 1];
            unsigned long long A0 = 0ull, A1 = 0ull, A2 = 0ull, A3 = 0ull;
            unsigned long long A4 = 0ull, A5 = 0ull, A6 = 0ull, A7 = 0ull;
#pragma unroll 1
            for (int q = s0; q < s1; q++) {
                const unsigned long long* gp = (const unsigned long long*)
                    &g_G[(g_nbrrank[q] * B_ + b0) * C_ + c2i];
                addf2(A0, gp[0 * 64]); addf2(A1, gp[1 * 64]);
                addf2(A2, gp[2 * 64]); addf2(A3, gp[3 * 64]);
                addf2(A4, gp[4 * 64]); addf2(A5, gp[5 * 64]);
                addf2(A6, gp[6 * 64]); addf2(A7, gp[7 * 64]);
            }
            float* hp = &g_H2[(b0 * N_ + n) * C_ + c2i];
            const int st = N_ * C_;
            float lo, hi;
            unpack2(A0, lo, hi); *(float2*)&hp[0 * st] = make_float2(fmaxf(lo + bc0, 0.f), fmaxf(hi + bc1, 0.f));
            unpack2(A1, lo, hi); *(float2*)&hp[1 * st] = make_float2(fmaxf(lo + bc0, 0.f), fmaxf(hi + bc1, 0.f));
            unpack2(A2, lo, hi); *(float2*)&hp[2 * st] = make_float2(fmaxf(lo + bc0, 0.f), fmaxf(hi + bc1, 0.f));
            unpack2(A3, lo, hi); *(float2*)&hp[3 * st] = make_float2(fmaxf(lo + bc0, 0.f), fmaxf(hi + bc1, 0.f));
            unpack2(A4, lo, hi); *(float2*)&hp[4 * st] = make_float2(fmaxf(lo + bc0, 0.f), fmaxf(hi + bc1, 0.f));
            unpack2(A5, lo, hi); *(float2*)&hp[5 * st] = make_float2(fmaxf(lo + bc0, 0.f), fmaxf(hi + bc1, 0.f));
            unpack2(A6, lo, hi); *(float2*)&hp[6 * st] = make_float2(fmaxf(lo + bc0, 0.f), fmaxf(hi + bc1, 0.f));
            unpack2(A7, lo, hi); *(float2*)&hp[7 * st] = make_float2(fmaxf(lo + bc0, 0.f), fmaxf(hi + bc1, 0.f));
        }
    }
    gsync(gen0, 4);

    // ======== P4: conv3 fused agg + f32x2 GEMM + relu (one 8-row tile/block) ==
    {
        int cnt3 = g_c3;
        int M3 = B_ * cnt3;
        int ntiles = (M3 + 7) >> 3;
        int grp = t >> 7, c = t & 127;
        float bc = b_conv[c];
        float (*As)[C_] = (float (*)[C_])sm;      // [8][128], group grp owns row grp
        for (int tile = bid; tile < ntiles; tile += NB) {
            int rr = tile * 8 + grp;
            int b = 0, i = 0;
            float acc = 0.f;
            if (rr < M3) {
                b = rr / cnt3; i = rr - b * cnt3;
                int n = g_list3[i];
                int s0 = g_rowptr[n], s1 = g_rowptr[n + 1];
#pragma unroll 8
                for (int q = s0; q < s1; q++)
                    acc += g_H2[(b * N_ + g_col[q]) * C_ + c];
            }
            As[grp][c] = acc;
            __syncthreads();
            unsigned long long acc2 = 0ull;
#pragma unroll 4
            for (int k = 0; k < C_; k += 4) {
                unsigned long long w01 = pack2(W_conv[(k + 0) * C_ + c],
                                               W_conv[(k + 1) * C_ + c]);
                unsigned long long w23 = pack2(W_conv[(k + 2) * C_ + c],
                                               W_conv[(k + 3) * C_ + c]);
                const ulonglong2 av = *(const ulonglong2*)&As[grp][k];
                ffma2(acc2, av.x, w01);
                ffma2(acc2, av.y, w23);
            }
            if (rr < M3)
                g_H3[(b * N_ + g_list3[i]) * C_ + c] =
                    fmaxf(unpack_sum(acc2) + bc, 0.f);
            __syncthreads();
        }
    }
    gsync(gen0, 5);

    // ======== P5: conv4 agg (node 0) + GEMM + classifier (blocks 0..63)
    //          || clear scratch for next launch (blocks 64..67)
    if (bid < B_) {
        float* part = sm;            // [8][128]
        float* s4   = sm + 1024;     // [128]
        float* red  = sm + 1152;     // [128]
        int ks = t >> 7, c = t & 127;
        int s0 = g_rowptr[0], s1 = g_rowptr[1];
        float acc = 0.f;
        for (int q = s0 + ks; q < s1; q += 8)
            acc += g_H3[(bid * N_ + g_col[q]) * C_ + c];
        part[ks * 128 + c] = acc;
        __syncthreads();
        if (t < 128) {
            float a = 0.f;
#pragma unroll
            for (int s = 0; s < 8; s++) a += part[s * 128 + t];
            s4[t] = a;
        }
        __syncthreads();
        int k0 = ks * 16;
        float p = 0.f;
#pragma unroll
        for (int k = k0; k < k0 + 16; k++) p += s4[k] * W_conv[k * C_ + c];
        __syncthreads();
        part[ks * 128 + c] = p;
        __syncthreads();
        if (t < 128) {
            float a2 = b_conv[t];
#pragma unroll
            for (int s = 0; s < 8; s++) a2 += part[s * 128 + t];
            red[t] = fmaxf(a2, 0.f) * W_cls[t];
        }
        __syncthreads();
#pragma unroll
        for (int off = 64; off > 0; off >>= 1) {
            if (t < off) red[t] += red[t + off];
            __syncthreads();
        }
        if (t == 0) out[bid] = red[0] + b_cls[0];
    } else if (bid == 64) {
        g_deg[t] = 0;
    } else if (bid == 65) {
        g_flag2[t] = 0;
    } else if (bid == 66) {
        g_flag3[t] = 0;
    } else if (bid == 67) {
        int nd = g_nd;
        if (t < nd) g_flagd[(int)g_dval[t]] = 0;
        __syncthreads();
        if (t == 0) g_nd = 0;
    }
}

extern "C" void kernel_launch(void* const* d_in, const int* in_sizes, int n_in,
                              void* d_out, int out_size) {
    (void)in_sizes; (void)n_in; (void)out_size;
    const float* x      = (const float*)d_in[0];
    const void*  eidx   = d_in[1];
    const float* W_emb  = (const float*)d_in[2];
    const float* b_emb  = (const float*)d_in[3];
    const float* W_conv = (const float*)d_in[4];
    const float* b_conv = (const float*)d_in[5];
    const float* W_cls  = (const float*)d_in[6];
    const float* b_cls  = (const float*)d_in[7];
    float* out = (float*)d_out;

    k_mega<<<NB, NT>>>(x, eidx, W_emb, b_emb, W_conv, b_conv, W_cls, b_cls, out);
}

// round 15
// speedup vs baseline: 1.9988x; 1.1690x over previous
#include <cuda_runtime.h>
#include <cuda_bf16.h>

// Problem constants (fixed by setup_inputs)
#define B_ 64
#define N_ 1024
#define E_ 16384
#define D_ 1024
#define C_ 128

#define NB 148          // 1 block per SM (B300:148, GB300:152) -> co-resident
#define NT 1024
#define FULLM 0xffffffffu
#define DMAXP1 (E_ + 1) // degree value range bound

// ---------------- device scratch (static, no allocations) ----------------
// deg/flag2/flag3/flagd/nd are cleared at the END of each launch (zero-init at load).
__device__ __align__(16) int g_src[E_];
__device__ __align__(16) int g_dst[E_];
__device__ int   g_deg[N_];
__device__ int   g_nrank[N_];           // node -> degree-rank
__device__ int   g_rowptr[N_ + 1];
__device__ int   g_cursor[N_];          // atomic fill cursors (= rowptr at P2 start)
__device__ int   g_col[E_];
__device__ int   g_nbrrank[E_];         // degree-rank of neighbor, per CSR slot
__device__ int   g_flag2[N_], g_flag3[N_];
__device__ int   g_list2[N_], g_list3[N_];
__device__ int   g_c2, g_c3;
__device__ int   g_flagd[DMAXP1];       // degree-value claimed flags
__device__ int   g_degrank[DMAXP1];     // degree value -> rank
__device__ float g_dval[N_];            // rank -> degree value (as float)
__device__ int   g_nd;                  // number of distinct degree values
__device__ __align__(16) float g_w0[B_ * C_];      // (h0 @ W_conv) per batch
__device__ __align__(16) float g_G[N_ * B_ * C_];  // G[rank][b][c]
__device__ __align__(16) float g_H2[B_ * N_ * C_]; // node-indexed (frontier2 rows)
__device__ __align__(16) float g_H3[B_ * N_ * C_]; // node-indexed (frontier3 rows)

// ---------------- software grid barrier (all blocks resident) ----------------
__device__ volatile unsigned g_gen;
__device__ unsigned          g_count;

__device__ __forceinline__ void gsync(unsigned gen0, unsigned k) {
    __syncthreads();
    if (threadIdx.x == 0) {
        __threadfence();
        if (atomicAdd(&g_count, 1u) == NB - 1u) {
            g_count = 0u;
            __threadfence();
            g_gen = gen0 + k;
        } else {
            while (g_gen != gen0 + k) { __nanosleep(32); }
        }
        __threadfence();
    }
    __syncthreads();
}

// ---------------- f32x2 packed helpers (Blackwell) ---------------------------
__device__ __forceinline__ void ffma2(unsigned long long& d,
                                      unsigned long long a, unsigned long long b) {
    asm("fma.rn.f32x2 %0, %1, %2, %0;" : "+l"(d) : "l"(a), "l"(b));
}
__device__ __forceinline__ void addf2(unsigned long long& d, unsigned long long a) {
    asm("add.rn.f32x2 %0, %0, %1;" : "+l"(d) : "l"(a));
}
__device__ __forceinline__ unsigned long long pack2(float lo, float hi) {
    unsigned long long r;
    asm("mov.b64 %0, {%1, %2};" : "=l"(r) : "f"(lo), "f"(hi));
    return r;
}
__device__ __forceinline__ void unpack2(unsigned long long v, float& lo, float& hi) {
    asm("mov.b64 {%0, %1}, %2;" : "=f"(lo), "=f"(hi) : "l"(v));
}
__device__ __forceinline__ float unpack_sum(unsigned long long v) {
    float lo, hi; unpack2(v, lo, hi);
    return lo + hi;
}

// inclusive scan across 1024 threads: shfl warp scan + warp-sum scan (2 barriers)
__device__ __forceinline__ int scan1(int v, int t, int* s) {
    int lane = t & 31, w = t >> 5;               // 32 warps
    int inc = v;
#pragma unroll
    for (int off = 1; off < 32; off <<= 1) {
        int u = __shfl_up_sync(FULLM, inc, off);
        if (lane >= off) inc += u;
    }
    if (lane == 31) s[w] = inc;
    __syncthreads();
    if (w == 0) {
        int x = s[lane];
#pragma unroll
        for (int off = 1; off < 32; off <<= 1) {
            int u = __shfl_up_sync(FULLM, x, off);
            if (lane >= off) x += u;
        }
        s[lane] = x;
    }
    __syncthreads();
    return inc + (w ? s[w - 1] : 0);
}

__device__ __forceinline__ void compact_flags(const int* flags, int* list, int* cnt_out,
                                              int t, int* s) {
    int f = flags[t];
    int incl = scan1(f, t, s);
    if (f) list[incl - 1] = t;
    if (t == NT - 1) *cnt_out = incl;
}

__global__ __launch_bounds__(NT) void k_mega(
    const float* __restrict__ x, const void* __restrict__ eidx,
    const float* __restrict__ W_emb,  const float* __restrict__ b_emb,
    const float* __restrict__ W_conv, const float* __restrict__ b_conv,
    const float* __restrict__ W_cls,  const float* __restrict__ b_cls,
    float* __restrict__ out)
{
    __shared__ __align__(16) float sm[8192];     // 32 KB, unioned across phases
    const int t   = threadIdx.x;
    const int bid = blockIdx.x;
    const unsigned gen0 = g_gen;

    // ======== P0: embedding + w0 (blocks 0..63, ONE batch each, float4 W_emb)
    //          || edge convert + deg + flag3 (blocks 64..79)
    if (bid < 64) {
        int b = bid;
        float* xs   = sm;             // [1024]
        float* part = sm + 1024;      // [32][128]
        float* h0   = sm + 5120;      // [128]
        xs[t] = x[b * D_ + t];
        __syncthreads();
        int c4 = (t & 31) * 4, ds = t >> 5;       // 32 c-quads x 32 d-slices
        int d0 = ds * 32;
        float4 A = {0.f, 0.f, 0.f, 0.f};
#pragma unroll 4
        for (int d = d0; d < d0 + 32; d++) {
            float4 w = *(const float4*)&W_emb[d * C_ + c4];   // coalesced 512B/warp
            float x0 = xs[d];
            A.x += x0 * w.x; A.y += x0 * w.y; A.z += x0 * w.z; A.w += x0 * w.w;
        }
        *(float4*)&part[ds * 128 + c4] = A;
        __syncthreads();
        int c = t & 127, g8 = t >> 7;
        float a = part[(g8 * 4 + 0) * 128 + c] + part[(g8 * 4 + 1) * 128 + c]
                + part[(g8 * 4 + 2) * 128 + c] + part[(g8 * 4 + 3) * 128 + c];
        __syncthreads();
        part[g8 * 128 + c] = a;                   // reuse rows 0..7
        __syncthreads();
        if (t < 128) {
            float h = b_emb[t];
#pragma unroll
            for (int s = 0; s < 8; s++) h += part[s * 128 + t];
            h0[t] = fmaxf(h, 0.f);
        }
        __syncthreads();
        // w0[b] = h0 @ W_conv, 8 k-slices of 16, coalesced scalar W_conv loads
        int ks = g8, k0 = ks * 16;
        float p = 0.f;
#pragma unroll
        for (int k = k0; k < k0 + 16; k++)
            p += h0[k] * W_conv[k * C_ + c];      // coalesced 128B/warp
        __syncthreads();
        part[ks * 128 + c] = p;
        __syncthreads();
        if (t < 128) {
            float a2 = 0.f;
#pragma unroll
            for (int s = 0; s < 8; s++) a2 += part[s * 128 + t];
            g_w0[b * C_ + t] = a2;
        }
    } else if (bid < 80) {
        int e = (bid - 64) * 1024 + t;            // 16*1024 == E_
        const unsigned* ew32 = (const unsigned*)eidx;
        int any = __syncthreads_or(ew32[2 * e + 1] != 0u);
        int is64 = !any;                          // int64 => high words all zero
        int s, d;
        if (is64) {
            const long long* p = (const long long*)eidx;
            s = (int)p[e]; d = (int)p[E_ + e];
        } else {
            const int* p = (const int*)eidx;
            s = p[e]; d = p[E_ + e];
        }
        g_src[e] = s; g_dst[e] = d;
        atomicAdd(&g_deg[d], 1);
        if (d == 0) g_flag3[s] = 1;
    }
    gsync(gen0, 1);

    // ======== P1: flag2 (0..15) || rowptr+cursor scan (16) || flag3 compact (17)
    //          || degree-rank claim + node-rank (18)
    if (bid < 16) {
        int e = bid * 1024 + t;
        if (g_flag3[g_dst[e]]) g_flag2[g_src[e]] = 1;
    } else if (bid == 16) {
        int d = g_deg[t];
        int incl = scan1(d, t, (int*)sm);
        g_rowptr[t + 1] = incl;
        g_cursor[t] = incl - d;                   // exclusive prefix = rowptr[t]
        if (t == 0) g_rowptr[0] = 0;
    } else if (bid == 17) {
        compact_flags(g_flag3, g_list3, &g_c3, t, (int*)sm);
    } else if (bid == 18) {
        int d = g_deg[t];                          // thread t handles node t
        int old = atomicExch(&g_flagd[d], 1);
        if (old == 0) {
            int r = atomicAdd(&g_nd, 1);
            g_degrank[d] = r;
            g_dval[r] = (float)d;
        }
        __syncthreads();
        g_nrank[t] = g_degrank[d];
    }
    gsync(gen0, 2);

    // ======== P2: csrfill edge-parallel (blocks 0..15, atomic cursors)
    //          || G-table build, 4-way split (16..146) || flag2 compact (147)
    if (bid < 16) {
        int e = bid * 1024 + t;
        int d = g_dst[e], s = g_src[e];
        int pos = atomicAdd(&g_cursor[d], 1);
        g_col[pos] = s;
        g_nbrrank[pos] = g_nrank[s];
    } else if (bid < 147) {
        // item = (rank, 16-row quarter); per thread: 2 rows of the quarter
        int nd4 = g_nd * 4;
        int c = t & 127, rg = t >> 7;             // 8 groups x 2 local rows
        float bc = b_conv[c];
        float (*As)[C_] = (float (*)[C_])sm;      // [16][128]
        for (int item = bid - 16; item < nd4; item += 131) {
            int rank = item >> 2, r0 = (item & 3) * 16;
            float dv = g_dval[rank];
            int lr = rg * 2;                      // local rows lr, lr+1
            As[lr + 0][c] = fmaxf(dv * g_w0[(r0 + lr + 0) * C_ + c] + bc, 0.f);
            As[lr + 1][c] = fmaxf(dv * g_w0[(r0 + lr + 1) * C_ + c] + bc, 0.f);
            __syncthreads();
            unsigned long long a0 = 0ull, a1 = 0ull;
#pragma unroll 4
            for (int k = 0; k < C_; k += 4) {
                unsigned long long w01 = pack2(W_conv[(k + 0) * C_ + c],
                                               W_conv[(k + 1) * C_ + c]);
                unsigned long long w23 = pack2(W_conv[(k + 2) * C_ + c],
                                               W_conv[(k + 3) * C_ + c]);
                const ulonglong2 av0 = *(const ulonglong2*)&As[lr + 0][k];
                const ulonglong2 av1 = *(const ulonglong2*)&As[lr + 1][k];
                ffma2(a0, av0.x, w01); ffma2(a0, av0.y, w23);
                ffma2(a1, av1.x, w01); ffma2(a1, av1.y, w23);
            }
            g_G[(rank * B_ + r0 + lr + 0) * C_ + c] = unpack_sum(a0);
            g_G[(rank * B_ + r0 + lr + 1) * C_ + c] = unpack_sum(a1);
            __syncthreads();
        }
    } else {
        compact_flags(g_flag2, g_list2, &g_c2, t, (int*)sm);
    }
    gsync(gen0, 3);

    // ======== P3: conv2 = packed f32x2 aggregation of G rows (coalesced) ======
    {
        int cnt2 = g_c2;
        int items = cnt2 * 8;                     // (i2, b-octet) work items
        int gid = bid * 16 + (t >> 6);            // NB*16 groups of 64 threads
        int c2i = (t & 63) * 2;                   // channel pair 2c, 2c+1
        float bc0 = b_conv[c2i], bc1 = b_conv[c2i + 1];
        for (int it = gid; it < items; it += NB * 16) {
            int i = it >> 3, b0 = (it & 7) * 8;
            int n = g_list2[i];
            int s0 = g_rowptr[n], s1 = g_rowptr[n + 1];
            unsigned long long A0 = 0ull, A1 = 0ull, A2 = 0ull, A3 = 0ull;
            unsigned long long A4 = 0ull, A5 = 0ull, A6 = 0ull, A7 = 0ull;
#pragma unroll 1
            for (int q = s0; q < s1; q++) {
                const unsigned long long* gp = (const unsigned long long*)
                    &g_G[(g_nbrrank[q] * B_ + b0) * C_ + c2i];
                addf2(A0, gp[0 * 64]); addf2(A1, gp[1 * 64]);
                addf2(A2, gp[2 * 64]); addf2(A3, gp[3 * 64]);
                addf2(A4, gp[4 * 64]); addf2(A5, gp[5 * 64]);
                addf2(A6, gp[6 * 64]); addf2(A7, gp[7 * 64]);
            }
            float* hp = &g_H2[(b0 * N_ + n) * C_ + c2i];
            const int st = N_ * C_;
            float lo, hi;
            unpack2(A0, lo, hi); *(float2*)&hp[0 * st] = make_float2(fmaxf(lo + bc0, 0.f), fmaxf(hi + bc1, 0.f));
            unpack2(A1, lo, hi); *(float2*)&hp[1 * st] = make_float2(fmaxf(lo + bc0, 0.f), fmaxf(hi + bc1, 0.f));
            unpack2(A2, lo, hi); *(float2*)&hp[2 * st] = make_float2(fmaxf(lo + bc0, 0.f), fmaxf(hi + bc1, 0.f));
            unpack2(A3, lo, hi); *(float2*)&hp[3 * st] = make_float2(fmaxf(lo + bc0, 0.f), fmaxf(hi + bc1, 0.f));
            unpack2(A4, lo, hi); *(float2*)&hp[4 * st] = make_float2(fmaxf(lo + bc0, 0.f), fmaxf(hi + bc1, 0.f));
            unpack2(A5, lo, hi); *(float2*)&hp[5 * st] = make_float2(fmaxf(lo + bc0, 0.f), fmaxf(hi + bc1, 0.f));
            unpack2(A6, lo, hi); *(float2*)&hp[6 * st] = make_float2(fmaxf(lo + bc0, 0.f), fmaxf(hi + bc1, 0.f));
            unpack2(A7, lo, hi); *(float2*)&hp[7 * st] = make_float2(fmaxf(lo + bc0, 0.f), fmaxf(hi + bc1, 0.f));
        }
    }
    gsync(gen0, 4);

    // ======== P4: conv3 fused agg + f32x2 GEMM + relu (one 8-row tile/block) ==
    {
        int cnt3 = g_c3;
        int M3 = B_ * cnt3;
        int ntiles = (M3 + 7) >> 3;
        int grp = t >> 7, c = t & 127;
        float bc = b_conv[c];
        float (*As)[C_] = (float (*)[C_])sm;      // [8][128], group grp owns row grp
        for (int tile = bid; tile < ntiles; tile += NB) {
            int rr = tile * 8 + grp;
            int b = 0, i = 0;
            float acc = 0.f;
            if (rr < M3) {
                b = rr / cnt3; i = rr - b * cnt3;
                int n = g_list3[i];
                int s0 = g_rowptr[n], s1 = g_rowptr[n + 1];
#pragma unroll 8
                for (int q = s0; q < s1; q++)
                    acc += g_H2[(b * N_ + g_col[q]) * C_ + c];
            }
            As[grp][c] = acc;
            __syncthreads();
            unsigned long long acc2 = 0ull;
#pragma unroll 4
            for (int k = 0; k < C_; k += 4) {
                unsigned long long w01 = pack2(W_conv[(k + 0) * C_ + c],
                                               W_conv[(k + 1) * C_ + c]);
                unsigned long long w23 = pack2(W_conv[(k + 2) * C_ + c],
                                               W_conv[(k + 3) * C_ + c]);
                const ulonglong2 av = *(const ulonglong2*)&As[grp][k];
                ffma2(acc2, av.x, w01);
                ffma2(acc2, av.y, w23);
            }
            if (rr < M3)
                g_H3[(b * N_ + g_list3[i]) * C_ + c] =
                    fmaxf(unpack_sum(acc2) + bc, 0.f);
            __syncthreads();
        }
    }
    gsync(gen0, 5);

    // ======== P5: conv4 agg (node 0) + GEMM + classifier (blocks 0..63)
    //          || clear scratch for next launch (blocks 64..67)
    if (bid < B_) {
        float* part = sm;            // [8][128]
        float* s4   = sm + 1024;     // [128]
        float* red  = sm + 1152;     // [128]
        int ks = t >> 7, c = t & 127;
        int s0 = g_rowptr[0], s1 = g_rowptr[1];
        float acc = 0.f;
        for (int q = s0 + ks; q < s1; q += 8)
            acc += g_H3[(bid * N_ + g_col[q]) * C_ + c];
        part[ks * 128 + c] = acc;
        __syncthreads();
        if (t < 128) {
            float a = 0.f;
#pragma unroll
            for (int s = 0; s < 8; s++) a += part[s * 128 + t];
            s4[t] = a;
        }
        __syncthreads();
        int k0 = ks * 16;
        float p = 0.f;
#pragma unroll
        for (int k = k0; k < k0 + 16; k++) p += s4[k] * W_conv[k * C_ + c];
        __syncthreads();
        part[ks * 128 + c] = p;
        __syncthreads();
        if (t < 128) {
            float a2 = b_conv[t];
#pragma unroll
            for (int s = 0; s < 8; s++) a2 += part[s * 128 + t];
            red[t] = fmaxf(a2, 0.f) * W_cls[t];
        }
        __syncthreads();
#pragma unroll
        for (int off = 64; off > 0; off >>= 1) {
            if (t < off) red[t] += red[t + off];
            __syncthreads();
        }
        if (t == 0) out[bid] = red[0] + b_cls[0];
    } else if (bid == 64) {
        g_deg[t] = 0;
    } else if (bid == 65) {
        g_flag2[t] = 0;
    } else if (bid == 66) {
        g_flag3[t] = 0;
    } else if (bid == 67) {
        int nd = g_nd;
        if (t < nd) g_flagd[(int)g_dval[t]] = 0;
        __syncthreads();
        if (t == 0) g_nd = 0;
    }
}

extern "C" void kernel_launch(void* const* d_in, const int* in_sizes, int n_in,
                              void* d_out, int out_size) {
    (void)in_sizes; (void)n_in; (void)out_size;
    const float* x      = (const float*)d_in[0];
    const void*  eidx   = d_in[1];
    const float* W_emb  = (const float*)d_in[2];
    const float* b_emb  = (const float*)d_in[3];
    const float* W_conv = (const float*)d_in[4];
    const float* b_conv = (const float*)d_in[5];
    const float* W_cls  = (const float*)d_in[6];
    const float* b_cls  = (const float*)d_in[7];
    float* out = (float*)d_out;

    k_mega<<<NB, NT>>>(x, eidx, W_emb, b_emb, W_conv, b_conv, W_cls, b_cls, out);
}